// round 3
// baseline (speedup 1.0000x reference)
#include <cuda_runtime.h>
#include <math_constants.h>

// VectorQuantizer — bit-exact replication of the jax-CPU (XLA/Eigen) reference:
//   dot   : sequential FMA chain over k=0..63 (Eigen gebp order), from 0
//   zsq   : scalar sequential rnd(mul)+rnd(add) over k=0..63
//   dist  : rnd( rnd(zsq - 2*dot) + csq )
//   argmin: strict <, ascending code index (first-min tie-break)
//   out   : rnd( z + rnd(q - z) )   (straight-through, elementwise fp32)
// fma.rn.f32x2 = two independent fma.rn lanes -> two codes per register,
// identical rounding to scalar chains at 2x throughput.

#define NROWS   65536
#define DIM     64
#define NCODES  1024
#define CHUNK   256
#define NCHUNKS (NCODES / CHUNK)
#define TPB     128
#define NBLOCKS (NROWS / TPB)

// dyn smem: pair-interleaved codes (CHUNK/2 pairs * DIM u64 = 64KB)
//           + csq chunk (CHUNK f) + idx (TPB i)
#define SMEM_BYTES ((CHUNK/2)*DIM*8 + CHUNK*4 + TPB*4)

typedef unsigned long long u64;

__device__ float  g_ctable[NCODES];
__device__ double g_partial[NBLOCKS];

__device__ __forceinline__ void fma2(u64& d, u64 a, u64 b) {
    asm("fma.rn.f32x2 %0, %1, %2, %0;" : "+l"(d) : "l"(a), "l"(b));
}
__device__ __forceinline__ u64 pack2(float x, float y) {
    u64 r; asm("mov.b64 %0, {%1, %2};" : "=l"(r) : "f"(x), "f"(y)); return r;
}
__device__ __forceinline__ float2 unpack2(u64 v) {
    float2 f; asm("mov.b64 {%0, %1}, %2;" : "=f"(f.x), "=f"(f.y) : "l"(v)); return f;
}

__global__ void vq_ctable_kernel(const float* __restrict__ emb) {
    int k = blockIdx.x * blockDim.x + threadIdx.x;
    if (k < NCODES) {
        const float* e = emb + (size_t)k * DIM;
        float acc = 0.f;                 // sequential rnd(mul)+rnd(add), k ascending
#pragma unroll
        for (int i = 0; i < DIM; i++)
            acc = __fadd_rn(acc, __fmul_rn(e[i], e[i]));
        g_ctable[k] = acc;
    }
}

__global__ __launch_bounds__(TPB) void vq_main_kernel(
    const float* __restrict__ z,
    const float* __restrict__ emb,
    float* __restrict__ out)
{
    extern __shared__ u64 sm_pairs[];                       // (CHUNK/2)*DIM u64
    float* s_c   = (float*)(sm_pairs + (CHUNK / 2) * DIM);  // CHUNK
    int*   s_idx = (int*)(s_c + CHUNK);                     // TPB

    const int tid = threadIdx.x;
    const int row = blockIdx.x * TPB + tid;

    // Load z row; zsq = sequential scalar mul+add (reference order);
    // zz[k] = {z_k, z_k} packed for dual-code f32x2 chains.
    float zsq = 0.f;
    u64 zz[DIM];
    {
        const float4* zp = (const float4*)(z + (size_t)row * DIM);
#pragma unroll
        for (int i = 0; i < DIM / 4; i++) {
            float4 v = zp[i];
            zsq = __fadd_rn(zsq, __fmul_rn(v.x, v.x));
            zsq = __fadd_rn(zsq, __fmul_rn(v.y, v.y));
            zsq = __fadd_rn(zsq, __fmul_rn(v.z, v.z));
            zsq = __fadd_rn(zsq, __fmul_rn(v.w, v.w));
            zz[4 * i + 0] = pack2(v.x, v.x);
            zz[4 * i + 1] = pack2(v.y, v.y);
            zz[4 * i + 2] = pack2(v.z, v.z);
            zz[4 * i + 3] = pack2(v.w, v.w);
        }
    }

    float best = CUDART_INF_F;
    int   bidx = 0;

    for (int ch = 0; ch < NCHUNKS; ch++) {
        // Stage chunk pair-interleaved: s_pairs[p*DIM + k] = {e[2p][k], e[2p+1][k]}
        {
            const float2* src = (const float2*)(emb + (size_t)ch * CHUNK * DIM);
            float* s32 = (float*)sm_pairs;
            for (int idx = tid; idx < CHUNK * DIM / 2; idx += TPB) {
                int c  = idx >> 5;            // code within chunk (32 float2/code)
                int kq = idx & 31;
                float2 e2 = src[c * 32 + kq];
                int p = c >> 1, l = c & 1;
                s32[((p * DIM + 2 * kq)     << 1) + l] = e2.x;
                s32[((p * DIM + 2 * kq + 1) << 1) + l] = e2.y;
            }
            for (int c = tid; c < CHUNK; c += TPB)
                s_c[c] = g_ctable[ch * CHUNK + c];
        }
        __syncthreads();

        for (int p0 = 0; p0 < CHUNK / 2; p0 += 4) {     // 4 pairs = 8 codes in flight
            const u64* e0 = sm_pairs + (size_t)(p0 + 0) * DIM;
            const u64* e1 = sm_pairs + (size_t)(p0 + 1) * DIM;
            const u64* e2 = sm_pairs + (size_t)(p0 + 2) * DIM;
            const u64* e3 = sm_pairs + (size_t)(p0 + 3) * DIM;
            u64 a0 = 0ull, a1 = 0ull, a2 = 0ull, a3 = 0ull;
#pragma unroll
            for (int k = 0; k < DIM; k += 2) {
                ulonglong2 E0 = *(const ulonglong2*)(e0 + k);   // broadcast LDS.128
                ulonglong2 E1 = *(const ulonglong2*)(e1 + k);
                ulonglong2 E2 = *(const ulonglong2*)(e2 + k);
                ulonglong2 E3 = *(const ulonglong2*)(e3 + k);
                fma2(a0, zz[k],     E0.x);  fma2(a1, zz[k],     E1.x);
                fma2(a2, zz[k],     E2.x);  fma2(a3, zz[k],     E3.x);
                fma2(a0, zz[k + 1], E0.y);  fma2(a1, zz[k + 1], E1.y);
                fma2(a2, zz[k + 1], E2.y);  fma2(a3, zz[k + 1], E3.y);
            }
            float2 d0 = unpack2(a0), d1 = unpack2(a1);
            float2 d2 = unpack2(a2), d3 = unpack2(a3);
            const int cl = p0 * 2;                 // local code base
            const int cg = ch * CHUNK + cl;        // global code base
            float dots[8] = {d0.x, d0.y, d1.x, d1.y, d2.x, d2.y, d3.x, d3.y};
#pragma unroll
            for (int j = 0; j < 8; j++) {          // ascending index: first-min ties
                float t    = __fadd_rn(zsq, __fmul_rn(dots[j], -2.0f));
                float dist = __fadd_rn(t, s_c[cl + j]);
                if (dist < best) { best = dist; bidx = cg + j; }
            }
        }
        __syncthreads();
    }

    s_idx[tid] = bidx;
    __syncthreads();

    // Output pass: out = rnd(z + rnd(q - z)); loss partial in double.
    double lsum = 0.0;
    {
        const float4* zb = (const float4*)(z + (size_t)blockIdx.x * TPB * DIM);
        const float4* eb = (const float4*)emb;
        float4* ob = (float4*)out + (size_t)blockIdx.x * TPB * (DIM / 4);
        for (int idx = tid; idx < TPB * (DIM / 4); idx += TPB) {
            int r  = idx >> 4;
            int c4 = idx & 15;
            float4 zv = zb[idx];
            float4 qv = eb[(size_t)s_idx[r] * (DIM / 4) + c4];
            float4 dv, ov;
            dv.x = __fadd_rn(qv.x, -zv.x);  ov.x = __fadd_rn(zv.x, dv.x);
            dv.y = __fadd_rn(qv.y, -zv.y);  ov.y = __fadd_rn(zv.y, dv.y);
            dv.z = __fadd_rn(qv.z, -zv.z);  ov.z = __fadd_rn(zv.z, dv.z);
            dv.w = __fadd_rn(qv.w, -zv.w);  ov.w = __fadd_rn(zv.w, dv.w);
            lsum += (double)__fmul_rn(dv.x, dv.x) + (double)__fmul_rn(dv.y, dv.y)
                  + (double)__fmul_rn(dv.z, dv.z) + (double)__fmul_rn(dv.w, dv.w);
            ob[idx] = ov;
        }
    }
    // Block-reduce doubles (deterministic tree).
    __shared__ double s_red[TPB / 32];
#pragma unroll
    for (int o = 16; o > 0; o >>= 1)
        lsum += __shfl_down_sync(0xffffffffu, lsum, o);
    if ((tid & 31) == 0) s_red[tid >> 5] = lsum;
    __syncthreads();
    if (tid == 0) {
        double t = 0.0;
#pragma unroll
        for (int i = 0; i < TPB / 32; i++) t += s_red[i];
        g_partial[blockIdx.x] = t;
    }
}

__global__ void vq_loss_kernel(float* __restrict__ out, int out_size) {
    if (threadIdx.x == 0) {
        double s = 0.0;
        for (int i = 0; i < NBLOCKS; i++) s += g_partial[i];
        float mf = (float)(s / (double)((size_t)NROWS * DIM));
        // loss = rnd(0.25*m + m); 0.25*m is exact (power of two)
        out[out_size - 1] = __fadd_rn(__fmul_rn(0.25f, mf), mf);
    }
}

extern "C" void kernel_launch(void* const* d_in, const int* in_sizes, int n_in,
                              void* d_out, int out_size) {
    const float* z   = (const float*)d_in[0];
    const float* emb = (const float*)d_in[1];
    if (n_in >= 2 && in_sizes[0] == NCODES * DIM && in_sizes[1] == NROWS * DIM) {
        const float* t = z; z = emb; emb = t;   // defensive order check
    }
    float* out = (float*)d_out;

    cudaFuncSetAttribute(vq_main_kernel,
                         cudaFuncAttributeMaxDynamicSharedMemorySize, SMEM_BYTES);

    vq_ctable_kernel<<<(NCODES + 127) / 128, 128>>>(emb);
    vq_main_kernel<<<NBLOCKS, TPB, SMEM_BYTES>>>(z, emb, out);
    vq_loss_kernel<<<1, 32>>>(out, out_size);
}

// round 4
// speedup vs baseline: 1.1908x; 1.1908x over previous
#include <cuda_runtime.h>
#include <math_constants.h>

// VectorQuantizer — bit-exact replication of the jax-CPU (XLA/Eigen) reference.
//   dot   : sequential FMA chain over k=0..63, from 0
//   zsq   : scalar sequential rnd(mul)+rnd(add) over k=0..63
//   csq   : scalar sequential rnd(mul)+rnd(add) over k=0..63
//   dist  : rnd( rnd(zsq - 2*dot) + csq )
//   argmin: strict <, ascending code index (first-min tie-break)
//   out   : rnd( z + rnd(q - z) )
// fma.rn.f32x2 = two independent fma.rn lanes -> two codes per register.
// Single fused kernel: per-chunk csq in-block, loss via exact fixed-point
// u64 atomics + last-block finalize (order-independent => deterministic).

#define NROWS   65536
#define DIM     64
#define NCODES  1024
#define CHUNK   256
#define NCHUNKS (NCODES / CHUNK)
#define TPB     128
#define NBLOCKS (NROWS / TPB)

// dyn smem: pair-interleaved codes ((CHUNK/2)*DIM u64 = 64KB) + csq + idx
#define SMEM_BYTES ((CHUNK/2)*DIM*8 + CHUNK*4 + TPB*4)

typedef unsigned long long u64;

__device__ u64          g_accum = 0;   // fixed-point 2^-40 loss accumulator
__device__ unsigned int g_done  = 0;   // blocks-finished counter

__device__ __forceinline__ void fma2(u64& d, u64 a, u64 b) {
    asm("fma.rn.f32x2 %0, %1, %2, %0;" : "+l"(d) : "l"(a), "l"(b));
}
__device__ __forceinline__ u64 pack2(float x, float y) {
    u64 r; asm("mov.b64 %0, {%1, %2};" : "=l"(r) : "f"(x), "f"(y)); return r;
}
__device__ __forceinline__ float2 unpack2(u64 v) {
    float2 f; asm("mov.b64 {%0, %1}, %2;" : "=f"(f.x), "=f"(f.y) : "l"(v)); return f;
}

__global__ __launch_bounds__(TPB) void vq_fused_kernel(
    const float* __restrict__ z,
    const float* __restrict__ emb,
    float* __restrict__ out,
    int out_size)
{
    extern __shared__ u64 sm_pairs[];                       // (CHUNK/2)*DIM u64
    float* s_c   = (float*)(sm_pairs + (CHUNK / 2) * DIM);  // CHUNK
    int*   s_idx = (int*)(s_c + CHUNK);                     // TPB

    const int tid = threadIdx.x;
    const int row = blockIdx.x * TPB + tid;

    // Load z row; zsq = sequential scalar mul+add (reference order);
    // zz[k] = {z_k, z_k} packed for dual-code f32x2 chains.
    float zsq = 0.f;
    u64 zz[DIM];
    {
        const float4* zp = (const float4*)(z + (size_t)row * DIM);
#pragma unroll
        for (int i = 0; i < DIM / 4; i++) {
            float4 v = zp[i];
            zsq = __fadd_rn(zsq, __fmul_rn(v.x, v.x));
            zsq = __fadd_rn(zsq, __fmul_rn(v.y, v.y));
            zsq = __fadd_rn(zsq, __fmul_rn(v.z, v.z));
            zsq = __fadd_rn(zsq, __fmul_rn(v.w, v.w));
            zz[4 * i + 0] = pack2(v.x, v.x);
            zz[4 * i + 1] = pack2(v.y, v.y);
            zz[4 * i + 2] = pack2(v.z, v.z);
            zz[4 * i + 3] = pack2(v.w, v.w);
        }
    }

    float best = CUDART_INF_F;
    int   bidx = 0;

    for (int ch = 0; ch < NCHUNKS; ch++) {
        // Stage chunk pair-interleaved: s_pairs[p*DIM+k] = {e[2p][k], e[2p+1][k]}
        {
            const float2* src = (const float2*)(emb + (size_t)ch * CHUNK * DIM);
            float* s32 = (float*)sm_pairs;
            for (int idx = tid; idx < CHUNK * DIM / 2; idx += TPB) {
                int c  = idx >> 5;            // code within chunk (32 float2/code)
                int kq = idx & 31;
                float2 e2 = src[c * 32 + kq];
                int p = c >> 1, l = c & 1;
                s32[((p * DIM + 2 * kq)     << 1) + l] = e2.x;
                s32[((p * DIM + 2 * kq + 1) << 1) + l] = e2.y;
            }
            // csq for this chunk: 2 codes/thread, exact sequential chain (L2-hot).
#pragma unroll
            for (int cc = 0; cc < CHUNK / TPB; cc++) {
                int c = cc * TPB + tid;
                const float4* e4 = (const float4*)(emb + ((size_t)ch * CHUNK + c) * DIM);
                float acc = 0.f;
#pragma unroll
                for (int i = 0; i < DIM / 4; i++) {
                    float4 v = e4[i];
                    acc = __fadd_rn(acc, __fmul_rn(v.x, v.x));
                    acc = __fadd_rn(acc, __fmul_rn(v.y, v.y));
                    acc = __fadd_rn(acc, __fmul_rn(v.z, v.z));
                    acc = __fadd_rn(acc, __fmul_rn(v.w, v.w));
                }
                s_c[c] = acc;
            }
        }
        __syncthreads();

        for (int p0 = 0; p0 < CHUNK / 2; p0 += 4) {     // 4 pairs = 8 codes in flight
            const u64* e0 = sm_pairs + (size_t)(p0 + 0) * DIM;
            const u64* e1 = sm_pairs + (size_t)(p0 + 1) * DIM;
            const u64* e2 = sm_pairs + (size_t)(p0 + 2) * DIM;
            const u64* e3 = sm_pairs + (size_t)(p0 + 3) * DIM;
            u64 a0 = 0ull, a1 = 0ull, a2 = 0ull, a3 = 0ull;
            // Software pipeline: load k+2 while FMAing k (hides LDS latency).
            ulonglong2 C0 = *(const ulonglong2*)(e0);
            ulonglong2 C1 = *(const ulonglong2*)(e1);
            ulonglong2 C2 = *(const ulonglong2*)(e2);
            ulonglong2 C3 = *(const ulonglong2*)(e3);
#pragma unroll
            for (int k = 0; k < DIM; k += 2) {
                ulonglong2 N0, N1, N2, N3;
                if (k + 2 < DIM) {
                    N0 = *(const ulonglong2*)(e0 + k + 2);
                    N1 = *(const ulonglong2*)(e1 + k + 2);
                    N2 = *(const ulonglong2*)(e2 + k + 2);
                    N3 = *(const ulonglong2*)(e3 + k + 2);
                }
                fma2(a0, zz[k],     C0.x);  fma2(a1, zz[k],     C1.x);
                fma2(a2, zz[k],     C2.x);  fma2(a3, zz[k],     C3.x);
                fma2(a0, zz[k + 1], C0.y);  fma2(a1, zz[k + 1], C1.y);
                fma2(a2, zz[k + 1], C2.y);  fma2(a3, zz[k + 1], C3.y);
                if (k + 2 < DIM) { C0 = N0; C1 = N1; C2 = N2; C3 = N3; }
            }
            float2 d0 = unpack2(a0), d1 = unpack2(a1);
            float2 d2 = unpack2(a2), d3 = unpack2(a3);
            const int cl = p0 * 2;                 // local code base
            const int cg = ch * CHUNK + cl;        // global code base
            float dots[8] = {d0.x, d0.y, d1.x, d1.y, d2.x, d2.y, d3.x, d3.y};
#pragma unroll
            for (int j = 0; j < 8; j++) {          // ascending index: first-min ties
                float t    = __fadd_rn(zsq, __fmul_rn(dots[j], -2.0f));
                float dist = __fadd_rn(t, s_c[cl + j]);
                if (dist < best) { best = dist; bidx = cg + j; }
            }
        }
        __syncthreads();
    }

    s_idx[tid] = bidx;
    __syncthreads();

    // Output pass: out = rnd(z + rnd(q - z)); loss partial in double.
    double lsum = 0.0;
    {
        const float4* zb = (const float4*)(z + (size_t)blockIdx.x * TPB * DIM);
        const float4* eb = (const float4*)emb;
        float4* ob = (float4*)out + (size_t)blockIdx.x * TPB * (DIM / 4);
        for (int idx = tid; idx < TPB * (DIM / 4); idx += TPB) {
            int r  = idx >> 4;
            int c4 = idx & 15;
            float4 zv = zb[idx];
            float4 qv = eb[(size_t)s_idx[r] * (DIM / 4) + c4];
            float4 dv, ov;
            dv.x = __fadd_rn(qv.x, -zv.x);  ov.x = __fadd_rn(zv.x, dv.x);
            dv.y = __fadd_rn(qv.y, -zv.y);  ov.y = __fadd_rn(zv.y, dv.y);
            dv.z = __fadd_rn(qv.z, -zv.z);  ov.z = __fadd_rn(zv.z, dv.z);
            dv.w = __fadd_rn(qv.w, -zv.w);  ov.w = __fadd_rn(zv.w, dv.w);
            lsum += (double)__fmul_rn(dv.x, dv.x) + (double)__fmul_rn(dv.y, dv.y)
                  + (double)__fmul_rn(dv.z, dv.z) + (double)__fmul_rn(dv.w, dv.w);
            ob[idx] = ov;
        }
    }
    // Deterministic block reduce (double), then one exact fixed-point atomic.
    __shared__ double s_red[TPB / 32];
#pragma unroll
    for (int o = 16; o > 0; o >>= 1)
        lsum += __shfl_down_sync(0xffffffffu, lsum, o);
    if ((tid & 31) == 0) s_red[tid >> 5] = lsum;
    __syncthreads();
    if (tid == 0) {
        double t = 0.0;
#pragma unroll
        for (int i = 0; i < TPB / 32; i++) t += s_red[i];
        // fixed point: 2^40 scale; block total ~8200 -> ~9e15; x512 < 2^63. exact.
        u64 q = (u64)(t * 1099511627776.0 + 0.5);
        atomicAdd(&g_accum, q);
        __threadfence();
        unsigned int done = atomicAdd(&g_done, 1u);
        if (done == NBLOCKS - 1) {                // last block finalizes
            u64 total = *(volatile u64*)&g_accum; // all adds visible (fence+atomic)
            double s = (double)total * (1.0 / 1099511627776.0);
            float mf = (float)(s / (double)((size_t)NROWS * DIM));
            out[out_size - 1] = __fadd_rn(__fmul_rn(0.25f, mf), mf);
            *(volatile u64*)&g_accum = 0ull;      // reset for next (graph) call
            *(volatile unsigned int*)&g_done = 0u;
        }
    }
}

extern "C" void kernel_launch(void* const* d_in, const int* in_sizes, int n_in,
                              void* d_out, int out_size) {
    const float* z   = (const float*)d_in[0];
    const float* emb = (const float*)d_in[1];
    if (n_in >= 2 && in_sizes[0] == NCODES * DIM && in_sizes[1] == NROWS * DIM) {
        const float* t = z; z = emb; emb = t;   // defensive order check
    }
    float* out = (float*)d_out;

    cudaFuncSetAttribute(vq_fused_kernel,
                         cudaFuncAttributeMaxDynamicSharedMemorySize, SMEM_BYTES);

    vq_fused_kernel<<<NBLOCKS, TPB, SMEM_BYTES>>>(z, emb, out, out_size);
}

// round 6
// speedup vs baseline: 1.1928x; 1.0016x over previous
#include <cuda_runtime.h>
#include <math_constants.h>

// VectorQuantizer — bit-exact replication of the jax-CPU (XLA/Eigen) reference.
//   dot   : sequential FMA chain over k=0..63, from 0
//   zsq   : scalar sequential rnd(mul)+rnd(add) over k=0..63
//   csq   : scalar sequential rnd(mul)+rnd(add) over k=0..63
//   dist  : rnd( rnd(zsq - 2*dot) + csq )
//   argmin: strict <, ascending code index (first-min tie-break)
//   out   : rnd( z + rnd(q - z) )
// fma.rn.f32x2 = two independent fma.rn lanes -> two codes per register.
// R5 change: __launch_bounds__(TPB, 2) -> 255-reg budget so zz[64] (128 regs)
// stays in registers. R4's 126-reg cap spilled z to local (L1=60%, fma=26%).

#define NROWS   65536
#define DIM     64
#define NCODES  1024
#define CHUNK   256
#define NCHUNKS (NCODES / CHUNK)
#define TPB     128
#define NBLOCKS (NROWS / TPB)

// dyn smem: pair-interleaved codes ((CHUNK/2)*DIM u64 = 64KB) + csq + idx
#define SMEM_BYTES ((CHUNK/2)*DIM*8 + CHUNK*4 + TPB*4)

typedef unsigned long long u64;

__device__ u64          g_accum = 0;   // fixed-point 2^-40 loss accumulator
__device__ unsigned int g_done  = 0;   // blocks-finished counter

__device__ __forceinline__ void fma2(u64& d, u64 a, u64 b) {
    asm("fma.rn.f32x2 %0, %1, %2, %0;" : "+l"(d) : "l"(a), "l"(b));
}
__device__ __forceinline__ u64 pack2(float x, float y) {
    u64 r; asm("mov.b64 %0, {%1, %2};" : "=l"(r) : "f"(x), "f"(y)); return r;
}
__device__ __forceinline__ float2 unpack2(u64 v) {
    float2 f; asm("mov.b64 {%0, %1}, %2;" : "=f"(f.x), "=f"(f.y) : "l"(v)); return f;
}

__global__ __launch_bounds__(TPB, 2) void vq_fused_kernel(
    const float* __restrict__ z,
    const float* __restrict__ emb,
    float* __restrict__ out,
    int out_size)
{
    extern __shared__ u64 sm_pairs[];                       // (CHUNK/2)*DIM u64
    float* s_c   = (float*)(sm_pairs + (CHUNK / 2) * DIM);  // CHUNK
    int*   s_idx = (int*)(s_c + CHUNK);                     // TPB

    const int tid = threadIdx.x;
    const int row = blockIdx.x * TPB + tid;

    // Load z row; zsq = sequential scalar mul+add (reference order);
    // zz[k] = {z_k, z_k} packed for dual-code f32x2 chains.
    float zsq = 0.f;
    u64 zz[DIM];
    {
        const float4* zp = (const float4*)(z + (size_t)row * DIM);
#pragma unroll
        for (int i = 0; i < DIM / 4; i++) {
            float4 v = zp[i];
            zsq = __fadd_rn(zsq, __fmul_rn(v.x, v.x));
            zsq = __fadd_rn(zsq, __fmul_rn(v.y, v.y));
            zsq = __fadd_rn(zsq, __fmul_rn(v.z, v.z));
            zsq = __fadd_rn(zsq, __fmul_rn(v.w, v.w));
            zz[4 * i + 0] = pack2(v.x, v.x);
            zz[4 * i + 1] = pack2(v.y, v.y);
            zz[4 * i + 2] = pack2(v.z, v.z);
            zz[4 * i + 3] = pack2(v.w, v.w);
        }
    }

    float best = CUDART_INF_F;
    int   bidx = 0;

    for (int ch = 0; ch < NCHUNKS; ch++) {
        // Stage chunk pair-interleaved: s_pairs[p*DIM+k] = {e[2p][k], e[2p+1][k]}
        {
            const float2* src = (const float2*)(emb + (size_t)ch * CHUNK * DIM);
            float* s32 = (float*)sm_pairs;
            for (int idx = tid; idx < CHUNK * DIM / 2; idx += TPB) {
                int c  = idx >> 5;            // code within chunk (32 float2/code)
                int kq = idx & 31;
                float2 e2 = src[c * 32 + kq];
                int p = c >> 1, l = c & 1;
                s32[((p * DIM + 2 * kq)     << 1) + l] = e2.x;
                s32[((p * DIM + 2 * kq + 1) << 1) + l] = e2.y;
            }
            // csq for this chunk: 2 codes/thread, exact sequential chain (L2-hot).
#pragma unroll
            for (int cc = 0; cc < CHUNK / TPB; cc++) {
                int c = cc * TPB + tid;
                const float4* e4 = (const float4*)(emb + ((size_t)ch * CHUNK + c) * DIM);
                float acc = 0.f;
#pragma unroll
                for (int i = 0; i < DIM / 4; i++) {
                    float4 v = e4[i];
                    acc = __fadd_rn(acc, __fmul_rn(v.x, v.x));
                    acc = __fadd_rn(acc, __fmul_rn(v.y, v.y));
                    acc = __fadd_rn(acc, __fmul_rn(v.z, v.z));
                    acc = __fadd_rn(acc, __fmul_rn(v.w, v.w));
                }
                s_c[c] = acc;
            }
        }
        __syncthreads();

        for (int p0 = 0; p0 < CHUNK / 2; p0 += 4) {     // 4 pairs = 8 codes in flight
            const u64* e0 = sm_pairs + (size_t)(p0 + 0) * DIM;
            const u64* e1 = sm_pairs + (size_t)(p0 + 1) * DIM;
            const u64* e2 = sm_pairs + (size_t)(p0 + 2) * DIM;
            const u64* e3 = sm_pairs + (size_t)(p0 + 3) * DIM;
            u64 a0 = 0ull, a1 = 0ull, a2 = 0ull, a3 = 0ull;
            // Software pipeline: load k+2 while FMAing k (hides LDS latency).
            ulonglong2 C0 = *(const ulonglong2*)(e0);
            ulonglong2 C1 = *(const ulonglong2*)(e1);
            ulonglong2 C2 = *(const ulonglong2*)(e2);
            ulonglong2 C3 = *(const ulonglong2*)(e3);
#pragma unroll
            for (int k = 0; k < DIM; k += 2) {
                ulonglong2 N0, N1, N2, N3;
                if (k + 2 < DIM) {
                    N0 = *(const ulonglong2*)(e0 + k + 2);
                    N1 = *(const ulonglong2*)(e1 + k + 2);
                    N2 = *(const ulonglong2*)(e2 + k + 2);
                    N3 = *(const ulonglong2*)(e3 + k + 2);
                }
                fma2(a0, zz[k],     C0.x);  fma2(a1, zz[k],     C1.x);
                fma2(a2, zz[k],     C2.x);  fma2(a3, zz[k],     C3.x);
                fma2(a0, zz[k + 1], C0.y);  fma2(a1, zz[k + 1], C1.y);
                fma2(a2, zz[k + 1], C2.y);  fma2(a3, zz[k + 1], C3.y);
                if (k + 2 < DIM) { C0 = N0; C1 = N1; C2 = N2; C3 = N3; }
            }
            float2 d0 = unpack2(a0), d1 = unpack2(a1);
            float2 d2 = unpack2(a2), d3 = unpack2(a3);
            const int cl = p0 * 2;                 // local code base
            const int cg = ch * CHUNK + cl;        // global code base
            float dots[8] = {d0.x, d0.y, d1.x, d1.y, d2.x, d2.y, d3.x, d3.y};
#pragma unroll
            for (int j = 0; j < 8; j++) {          // ascending index: first-min ties
                float t    = __fadd_rn(zsq, __fmul_rn(dots[j], -2.0f));
                float dist = __fadd_rn(t, s_c[cl + j]);
                if (dist < best) { best = dist; bidx = cg + j; }
            }
        }
        __syncthreads();
    }

    s_idx[tid] = bidx;
    __syncthreads();

    // Output pass: out = rnd(z + rnd(q - z)); loss partial in double.
    double lsum = 0.0;
    {
        const float4* zb = (const float4*)(z + (size_t)blockIdx.x * TPB * DIM);
        const float4* eb = (const float4*)emb;
        float4* ob = (float4*)out + (size_t)blockIdx.x * TPB * (DIM / 4);
        for (int idx = tid; idx < TPB * (DIM / 4); idx += TPB) {
            int r  = idx >> 4;
            int c4 = idx & 15;
            float4 zv = zb[idx];
            float4 qv = eb[(size_t)s_idx[r] * (DIM / 4) + c4];
            float4 dv, ov;
            dv.x = __fadd_rn(qv.x, -zv.x);  ov.x = __fadd_rn(zv.x, dv.x);
            dv.y = __fadd_rn(qv.y, -zv.y);  ov.y = __fadd_rn(zv.y, dv.y);
            dv.z = __fadd_rn(qv.z, -zv.z);  ov.z = __fadd_rn(zv.z, dv.z);
            dv.w = __fadd_rn(qv.w, -zv.w);  ov.w = __fadd_rn(zv.w, dv.w);
            lsum += (double)__fmul_rn(dv.x, dv.x) + (double)__fmul_rn(dv.y, dv.y)
                  + (double)__fmul_rn(dv.z, dv.z) + (double)__fmul_rn(dv.w, dv.w);
            ob[idx] = ov;
        }
    }
    // Deterministic block reduce (double), then one exact fixed-point atomic.
    __shared__ double s_red[TPB / 32];
#pragma unroll
    for (int o = 16; o > 0; o >>= 1)
        lsum += __shfl_down_sync(0xffffffffu, lsum, o);
    if ((tid & 31) == 0) s_red[tid >> 5] = lsum;
    __syncthreads();
    if (tid == 0) {
        double t = 0.0;
#pragma unroll
        for (int i = 0; i < TPB / 32; i++) t += s_red[i];
        // fixed point: 2^40 scale; block total ~8200 -> ~9e15; x512 < 2^63. exact.
        u64 q = (u64)(t * 1099511627776.0 + 0.5);
        atomicAdd(&g_accum, q);
        __threadfence();
        unsigned int done = atomicAdd(&g_done, 1u);
        if (done == NBLOCKS - 1) {                // last block finalizes
            u64 total = *(volatile u64*)&g_accum; // all adds visible (fence+atomic)
            double s = (double)total * (1.0 / 1099511627776.0);
            float mf = (float)(s / (double)((size_t)NROWS * DIM));
            out[out_size - 1] = __fadd_rn(__fmul_rn(0.25f, mf), mf);
            *(volatile u64*)&g_accum = 0ull;      // reset for next (graph) call
            *(volatile unsigned int*)&g_done = 0u;
        }
    }
}

extern "C" void kernel_launch(void* const* d_in, const int* in_sizes, int n_in,
                              void* d_out, int out_size) {
    const float* z   = (const float*)d_in[0];
    const float* emb = (const float*)d_in[1];
    if (n_in >= 2 && in_sizes[0] == NCODES * DIM && in_sizes[1] == NROWS * DIM) {
        const float* t = z; z = emb; emb = t;   // defensive order check
    }
    float* out = (float*)d_out;

    cudaFuncSetAttribute(vq_fused_kernel,
                         cudaFuncAttributeMaxDynamicSharedMemorySize, SMEM_BYTES);

    vq_fused_kernel<<<NBLOCKS, TPB, SMEM_BYTES>>>(z, emb, out, out_size);
}